// round 13
// baseline (speedup 1.0000x reference)
#include <cuda_runtime.h>
#include <cuda_bf16.h>
#include <cstdint>

// Problem constants
#define NN 50000
#define EE 600000
#define DD 128
#define HH 128
#define CC 64
#define LLAYERS 3
#define XCW (DD + LLAYERS * HH)   // 512

// weight split buffer offsets (elements)
#define WG_OFF(i) ((i) * 16384)
#define W1_OFF    49152
#define W2_OFF    114688
#define WB_TOT    122880

// ---------------- scratch (device globals; no runtime allocation) ----------
__device__ int   g_hist[NN];
__device__ int   g_rowptr[NN + 1];
__device__ int   g_cursor[NN];
__device__ int   g_csr_src[EE];
__device__ float g_dinv[NN];
__device__ float g_hW[(size_t)NN * HH];     // u = dinv * (h @ W)
__device__ __nv_bfloat16 g_xc_hi[(size_t)NN * XCW];
__device__ __nv_bfloat16 g_xc_lo[(size_t)NN * XCW];
__device__ __nv_bfloat16 g_z_hi[(size_t)NN * HH];
__device__ __nv_bfloat16 g_z_lo[(size_t)NN * HH];
__device__ __nv_bfloat16 g_wb_hi[WB_TOT];
__device__ __nv_bfloat16 g_wb_lo[WB_TOT];

__device__ __forceinline__ void split2(float2 v, __nv_bfloat162& h, __nv_bfloat162& l) {
    h = __float22bfloat162_rn(v);
    float2 f = __bfloat1622float2(h);
    l = __float22bfloat162_rn(make_float2(v.x - f.x, v.y - f.y));
}

// ---------------- setup kernels ---------------------------------------------
// fused: hist count (hist pre-zeroed by memset), split weights, copy/split x
__global__ void k_initcopy(const float* __restrict__ x,
                           const int* __restrict__ ei,
                           const float* __restrict__ Wg,
                           const float* __restrict__ W1,
                           const float* __restrict__ W2) {
    int idx = blockIdx.x * blockDim.x + threadIdx.x;
    if (idx < EE) atomicAdd(&g_hist[ei[EE + idx]], 1);
    if (idx < WB_TOT) {
        float v;
        if (idx < W1_OFF) v = Wg[idx];
        else if (idx < W2_OFF) v = W1[idx - W1_OFF];
        else v = W2[idx - W2_OFF];
        __nv_bfloat16 h = __float2bfloat16(v);
        g_wb_hi[idx] = h;
        g_wb_lo[idx] = __float2bfloat16(v - __bfloat162float(h));
    }
    if (idx >= NN * 32) return;
    int n = idx >> 5;
    int c4 = (idx & 31) << 2;
    float4 v = ((const float4*)x)[idx];
    __nv_bfloat162 h0, l0, h1, l1;
    split2(make_float2(v.x, v.y), h0, l0);
    split2(make_float2(v.z, v.w), h1, l1);
    size_t base = (size_t)n * XCW + c4;
    *(__nv_bfloat162*)&g_xc_hi[base]     = h0;
    *(__nv_bfloat162*)&g_xc_hi[base + 2] = h1;
    *(__nv_bfloat162*)&g_xc_lo[base]     = l0;
    *(__nv_bfloat162*)&g_xc_lo[base + 2] = l1;
}

// single-block exclusive scan over g_hist -> g_rowptr / g_cursor; also dinv
__global__ __launch_bounds__(1024) void k_scan() {
    const int CH = (NN + 1023) / 1024;   // 49
    int tid = threadIdx.x;
    int lane = tid & 31;
    int wid = tid >> 5;
    int beg = tid * CH;
    int end = min(beg + CH, NN);

    int s = 0;
    for (int i = beg; i < end; i++) s += g_hist[i];

    int v = s;
    #pragma unroll
    for (int o = 1; o < 32; o <<= 1) {
        int t = __shfl_up_sync(0xffffffffu, v, o);
        if (lane >= o) v += t;
    }
    __shared__ int ws[32];
    if (lane == 31) ws[wid] = v;
    __syncthreads();
    if (wid == 0) {
        int w = ws[lane];
        #pragma unroll
        for (int o = 1; o < 32; o <<= 1) {
            int t = __shfl_up_sync(0xffffffffu, w, o);
            if (lane >= o) w += t;
        }
        ws[lane] = w;
    }
    __syncthreads();
    int base = (wid ? ws[wid - 1] : 0) + v - s;   // exclusive offset
    for (int i = beg; i < end; i++) {
        g_rowptr[i] = base;
        g_cursor[i] = base;
        base += g_hist[i];
        g_dinv[i] = rsqrtf((float)(g_hist[i] + 1));
    }
    if (tid == 1023) g_rowptr[NN] = EE;
}

__global__ void k_fill(const int* __restrict__ ei) {
    int e = blockIdx.x * blockDim.x + threadIdx.x;
    if (e >= EE) return;
    int d = ei[EE + e];
    int pos = atomicAdd(&g_cursor[d], 1);
    g_csr_src[pos] = ei[e];
}

// ---------------- fused gather + LN + ReLU -----------------------------------
// warp per node d: acc = u[d] + sum_{s in N(d)} u[s] (MLP-8 group loads);
// then dinv[d]*acc + bias, LayerNorm, ReLU -> xc hi/lo
__global__ void k_gather_ln(const float* __restrict__ bg,
                            const float* __restrict__ lng,
                            const float* __restrict__ lnb,
                            int layer) {
    int t = blockIdx.x * blockDim.x + threadIdx.x;
    int w = t >> 5;
    if (w >= NN) return;
    int lane = t & 31;

    const float4* U = (const float4*)g_hW;
    float4 acc = __ldg(&U[(size_t)w * 32 + lane]);   // self term u[d]
    int pos = __ldg(&g_rowptr[w]);
    int end = __ldg(&g_rowptr[w + 1]);

    for (; pos + 8 <= end; pos += 8) {
        int sx[8];
        #pragma unroll
        for (int j = 0; j < 8; j++) sx[j] = __ldg(&g_csr_src[pos + j]);
        float4 vv[8];
        #pragma unroll
        for (int j = 0; j < 8; j++) vv[j] = __ldg(&U[(size_t)sx[j] * 32 + lane]);
        float4 a0, a1;
        a0.x = (vv[0].x + vv[1].x) + (vv[2].x + vv[3].x);
        a0.y = (vv[0].y + vv[1].y) + (vv[2].y + vv[3].y);
        a0.z = (vv[0].z + vv[1].z) + (vv[2].z + vv[3].z);
        a0.w = (vv[0].w + vv[1].w) + (vv[2].w + vv[3].w);
        a1.x = (vv[4].x + vv[5].x) + (vv[6].x + vv[7].x);
        a1.y = (vv[4].y + vv[5].y) + (vv[6].y + vv[7].y);
        a1.z = (vv[4].z + vv[5].z) + (vv[6].z + vv[7].z);
        a1.w = (vv[4].w + vv[5].w) + (vv[6].w + vv[7].w);
        acc.x += a0.x + a1.x;
        acc.y += a0.y + a1.y;
        acc.z += a0.z + a1.z;
        acc.w += a0.w + a1.w;
    }
    if (pos + 4 <= end) {
        int s0 = __ldg(&g_csr_src[pos]);
        int s1 = __ldg(&g_csr_src[pos + 1]);
        int s2 = __ldg(&g_csr_src[pos + 2]);
        int s3 = __ldg(&g_csr_src[pos + 3]);
        float4 v0 = __ldg(&U[(size_t)s0 * 32 + lane]);
        float4 v1 = __ldg(&U[(size_t)s1 * 32 + lane]);
        float4 v2 = __ldg(&U[(size_t)s2 * 32 + lane]);
        float4 v3 = __ldg(&U[(size_t)s3 * 32 + lane]);
        acc.x += (v0.x + v1.x) + (v2.x + v3.x);
        acc.y += (v0.y + v1.y) + (v2.y + v3.y);
        acc.z += (v0.z + v1.z) + (v2.z + v3.z);
        acc.w += (v0.w + v1.w) + (v2.w + v3.w);
        pos += 4;
    }
    for (; pos < end; pos++) {
        int s = __ldg(&g_csr_src[pos]);
        float4 v = __ldg(&U[(size_t)s * 32 + lane]);
        acc.x += v.x; acc.y += v.y; acc.z += v.z; acc.w += v.w;
    }

    float dd = __ldg(&g_dinv[w]);
    float4 bb = ((const float4*)(bg + layer * HH))[lane];
    acc.x = fmaf(acc.x, dd, bb.x);
    acc.y = fmaf(acc.y, dd, bb.y);
    acc.z = fmaf(acc.z, dd, bb.z);
    acc.w = fmaf(acc.w, dd, bb.w);

    float s = acc.x + acc.y + acc.z + acc.w;
    #pragma unroll
    for (int o = 16; o; o >>= 1) s += __shfl_xor_sync(0xffffffffu, s, o);
    float mu = s * (1.0f / HH);

    float dx = acc.x - mu, dy = acc.y - mu, dz = acc.z - mu, dw = acc.w - mu;
    float q = dx * dx + dy * dy + dz * dz + dw * dw;
    #pragma unroll
    for (int o = 16; o; o >>= 1) q += __shfl_xor_sync(0xffffffffu, q, o);
    float inv = rsqrtf(q * (1.0f / HH) + 1e-5f);

    float4 g4 = ((const float4*)(lng + layer * HH))[lane];
    float4 b4 = ((const float4*)(lnb + layer * HH))[lane];
    float4 o4;
    o4.x = fmaxf(fmaf(g4.x * dx, inv, b4.x), 0.0f);
    o4.y = fmaxf(fmaf(g4.y * dy, inv, b4.y), 0.0f);
    o4.z = fmaxf(fmaf(g4.z * dz, inv, b4.z), 0.0f);
    o4.w = fmaxf(fmaf(g4.w * dw, inv, b4.w), 0.0f);

    __nv_bfloat162 h0, l0, h1, l1;
    split2(make_float2(o4.x, o4.y), h0, l0);
    split2(make_float2(o4.z, o4.w), h1, l1);
    size_t base = (size_t)w * XCW + (1 + layer) * HH + lane * 4;
    *(__nv_bfloat162*)&g_xc_hi[base]     = h0;
    *(__nv_bfloat162*)&g_xc_hi[base + 2] = h1;
    *(__nv_bfloat162*)&g_xc_lo[base]     = l0;
    *(__nv_bfloat162*)&g_xc_lo[base + 2] = l1;
}

// ==================== cp.async bf16-split GEMM (128x64 tile, 2-stage) =======
__device__ __forceinline__ uint32_t smem_u32(const void* p) {
    uint32_t a;
    asm("{ .reg .u64 t; cvta.to.shared.u64 t, %1; cvt.u32.u64 %0, t; }"
        : "=r"(a) : "l"(p));
    return a;
}

__device__ __forceinline__ void ldm_x4(uint32_t* r, uint32_t addr) {
    asm volatile("ldmatrix.sync.aligned.m8n8.x4.shared.b16 {%0,%1,%2,%3}, [%4];"
                 : "=r"(r[0]), "=r"(r[1]), "=r"(r[2]), "=r"(r[3]) : "r"(addr));
}

__device__ __forceinline__ void ldm_x4_t(uint32_t* r, uint32_t addr) {
    asm volatile("ldmatrix.sync.aligned.m8n8.x4.trans.shared.b16 {%0,%1,%2,%3}, [%4];"
                 : "=r"(r[0]), "=r"(r[1]), "=r"(r[2]), "=r"(r[3]) : "r"(addr));
}

__device__ __forceinline__ void mma_bf16(float* d, const uint32_t* a, const uint32_t* b) {
    asm volatile("mma.sync.aligned.m16n8k16.row.col.f32.bf16.bf16.f32 "
                 "{%0,%1,%2,%3}, {%4,%5,%6,%7}, {%8,%9}, {%0,%1,%2,%3};"
                 : "+f"(d[0]), "+f"(d[1]), "+f"(d[2]), "+f"(d[3])
                 : "r"(a[0]), "r"(a[1]), "r"(a[2]), "r"(a[3]),
                   "r"(b[0]), "r"(b[1]));
}

__device__ __forceinline__ void cp16(uint32_t dst, const void* src, int sz) {
    asm volatile("cp.async.cg.shared.global [%0], [%1], 16, %2;"
                 :: "r"(dst), "l"(src), "r"(sz) : "memory");
}
#define CP_COMMIT() asm volatile("cp.async.commit_group;" ::: "memory")
#define CP_WAIT1()  asm volatile("cp.async.wait_group 1;" ::: "memory")

// smem layout (per stage): A hi rows 0..127 (80B stride), A lo at +10240;
// B hi 32x128B swizzled, B lo at +4096.
#define AST  20480
#define BOFF 40960
#define BST  8192
#define SMEM_TOT (BOFF + 2 * BST)   // 57344

__device__ __forceinline__ void issue_chunk(
    const __nv_bfloat16* __restrict__ A_hi, const __nv_bfloat16* __restrict__ A_lo,
    int lda,
    const __nv_bfloat16* __restrict__ B_hi, const __nv_bfloat16* __restrict__ B_lo,
    int ldb, int bcol, int M, int row0, int k0,
    uint32_t as, uint32_t bs, int tid) {
    #pragma unroll
    for (int j = 0; j < 2; j++) {
        int v = tid + j * 256;
        int r = v >> 2, seg = v & 3;
        int gr = row0 + r;
        int sz = (gr < M) ? 16 : 0;
        if (gr >= M) gr = 0;
        size_t so = (size_t)gr * lda + k0 + seg * 8;
        uint32_t dd = as + (uint32_t)(r * 80 + seg * 16);
        cp16(dd, A_hi + so, sz);
        cp16(dd + 10240, A_lo + so, sz);
    }
    {
        int k = tid >> 3, seg = tid & 7;
        int sw = seg ^ (k & 7);
        size_t so = (size_t)(k0 + k) * ldb + bcol + seg * 8;
        uint32_t dd = bs + (uint32_t)(k * 128 + sw * 16);
        cp16(dd, B_hi + so, 16);
        cp16(dd + 4096, B_lo + so, 16);
    }
}

// 2-stage cp.async mainloop: C-tile 128x64, BK=32, 8 warps (4x2).
__device__ __forceinline__ void gemm64_loop(
    const __nv_bfloat16* __restrict__ A_hi, const __nv_bfloat16* __restrict__ A_lo,
    int lda,
    const __nv_bfloat16* __restrict__ B_hi, const __nv_bfloat16* __restrict__ B_lo,
    int ldb, int bcol, int M, int nk, int row0, uint32_t smb,
    int tid, int warp_m, int warp_n, int lane,
    float (&d)[2][4][4]) {

    issue_chunk(A_hi, A_lo, lda, B_hi, B_lo, ldb, bcol, M, row0, 0,
                smb, smb + BOFF, tid);
    CP_COMMIT();
    if (nk > 1)
        issue_chunk(A_hi, A_lo, lda, B_hi, B_lo, ldb, bcol, M, row0, 32,
                    smb + AST, smb + BOFF + BST, tid);
    CP_COMMIT();

    for (int ck = 0; ck < nk; ck++) {
        CP_WAIT1();
        __syncthreads();

        uint32_t ab = smb + (uint32_t)((ck & 1) * AST);
        uint32_t bb = smb + (uint32_t)(BOFF + (ck & 1) * BST);
        #pragma unroll
        for (int ks = 0; ks < 2; ks++) {
            int kb = ks * 16;
            uint32_t afr[2][2][4];
            #pragma unroll
            for (int h = 0; h < 2; h++)
                #pragma unroll
                for (int mf = 0; mf < 2; mf++) {
                    int rr = warp_m * 32 + mf * 16 + (lane & 7) + ((lane >> 3) & 1) * 8;
                    int cc = kb + (lane >> 4) * 8;
                    ldm_x4(afr[h][mf], ab + (uint32_t)((h * 128 + rr) * 80 + cc * 2));
                }
            uint32_t bfr[2][4][2];
            #pragma unroll
            for (int h = 0; h < 2; h++)
                #pragma unroll
                for (int nn = 0; nn < 2; nn++) {
                    int kr = kb + ((lane >> 3) & 1) * 8 + (lane & 7);
                    int nc = warp_n * 32 + nn * 16 + (lane >> 4) * 8;
                    int chv = (nc >> 3) ^ (kr & 7);
                    uint32_t r4[4];
                    ldm_x4_t(r4, bb + (uint32_t)(h * 4096 + kr * 128 + (chv << 4)));
                    bfr[h][nn * 2][0] = r4[0]; bfr[h][nn * 2][1] = r4[1];
                    bfr[h][nn * 2 + 1][0] = r4[2]; bfr[h][nn * 2 + 1][1] = r4[3];
                }
            #pragma unroll
            for (int mf = 0; mf < 2; mf++)
                #pragma unroll
                for (int nf = 0; nf < 4; nf++) {
                    mma_bf16(d[mf][nf], afr[0][mf], bfr[0][nf]);
                    mma_bf16(d[mf][nf], afr[0][mf], bfr[1][nf]);
                    mma_bf16(d[mf][nf], afr[1][mf], bfr[0][nf]);
                }
        }
        __syncthreads();

        if (ck + 2 < nk)
            issue_chunk(A_hi, A_lo, lda, B_hi, B_lo, ldb, bcol, M, row0,
                        (ck + 2) * 32,
                        smb + (uint32_t)((ck & 1) * AST),
                        smb + (uint32_t)(BOFF + (ck & 1) * BST), tid);
        CP_COMMIT();
    }
}

// CM=0: layer GEMM (scale by dinv, store u -> g_hW); A = xc + a_off
// CM=1: W1 GEMM (bias+relu, store z hi/lo)
template <int CM>
__global__ __launch_bounds__(256, 3) void k_gemm64(
    int a_off, int lda, int wb_off, int ldb,
    const float* __restrict__ bias, int M, int nk) {

    extern __shared__ __align__(16) char sm[];

    const __nv_bfloat16* A_hi = g_xc_hi + a_off;    // resolved in device code
    const __nv_bfloat16* A_lo = g_xc_lo + a_off;

    int tid = threadIdx.x;
    int wid = tid >> 5;
    int lane = tid & 31;
    int warp_m = wid >> 1;     // 0..3
    int warp_n = wid & 1;      // 0..1
    int row0 = blockIdx.y * 128;
    int bcol = blockIdx.x * 64;
    uint32_t smb = smem_u32(sm);

    float d[2][4][4];
    #pragma unroll
    for (int mf = 0; mf < 2; mf++)
        #pragma unroll
        for (int nf = 0; nf < 4; nf++)
            #pragma unroll
            for (int j = 0; j < 4; j++) d[mf][nf][j] = 0.0f;

    gemm64_loop(A_hi, A_lo, lda, g_wb_hi + wb_off, g_wb_lo + wb_off, ldb, bcol,
                M, nk, row0, smb, tid, warp_m, warp_n, lane, d);

    #pragma unroll
    for (int mf = 0; mf < 2; mf++) {
        int rbase = row0 + warp_m * 32 + mf * 16 + (lane >> 2);
        #pragma unroll
        for (int half = 0; half < 2; half++) {
            int gr = rbase + half * 8;
            if (gr < M) {
                float sc = (CM == 0) ? __ldg(&g_dinv[gr]) : 1.0f;
                #pragma unroll
                for (int nf = 0; nf < 4; nf++) {
                    int gc = bcol + warp_n * 32 + nf * 8 + (lane & 3) * 2;
                    float2 v = make_float2(d[mf][nf][half * 2], d[mf][nf][half * 2 + 1]);
                    if (CM == 0) {
                        v.x *= sc; v.y *= sc;
                        *(float2*)(g_hW + (size_t)gr * HH + gc) = v;
                    } else {
                        v.x = fmaxf(v.x + bias[gc], 0.f);
                        v.y = fmaxf(v.y + bias[gc + 1], 0.f);
                        __nv_bfloat162 h, l;
                        split2(v, h, l);
                        *(__nv_bfloat162*)&g_z_hi[(size_t)gr * HH + gc] = h;
                        *(__nv_bfloat162*)&g_z_lo[(size_t)gr * HH + gc] = l;
                    }
                }
            }
        }
    }
}

// ===== W2 GEMM (128x64) with fused bias + softmax epilogue -> out ===========
__global__ __launch_bounds__(256, 3) void k_gemm_w2s(
    const float* __restrict__ bias, float* __restrict__ out, int M) {

    extern __shared__ __align__(16) char sm[];
    constexpr int CS_LD = 66;
    float* Cs = (float*)sm;          // 128*66*4 = 33792 <= SMEM_TOT

    int tid = threadIdx.x;
    int wid = tid >> 5;
    int lane = tid & 31;
    int warp_m = wid >> 1;
    int warp_n = wid & 1;
    int row0 = blockIdx.x * 128;
    uint32_t smb = smem_u32(sm);

    float d[2][4][4];
    #pragma unroll
    for (int mf = 0; mf < 2; mf++)
        #pragma unroll
        for (int nf = 0; nf < 4; nf++)
            #pragma unroll
            for (int j = 0; j < 4; j++) d[mf][nf][j] = 0.0f;

    gemm64_loop(g_z_hi, g_z_lo, HH, g_wb_hi + W2_OFF, g_wb_lo + W2_OFF, CC, 0,
                M, 4, row0, smb, tid, warp_m, warp_n, lane, d);
    // loop ends with a __syncthreads after final compute: smem reusable

    #pragma unroll
    for (int mf = 0; mf < 2; mf++) {
        int rl = warp_m * 32 + mf * 16 + (lane >> 2);
        #pragma unroll
        for (int half = 0; half < 2; half++) {
            int r = rl + half * 8;
            #pragma unroll
            for (int nf = 0; nf < 4; nf++) {
                int c = warp_n * 32 + nf * 8 + (lane & 3) * 2;
                Cs[r * CS_LD + c]     = d[mf][nf][half * 2]     + bias[c];
                Cs[r * CS_LD + c + 1] = d[mf][nf][half * 2 + 1] + bias[c + 1];
            }
        }
    }
    __syncthreads();

    for (int it = 0; it < 16; it++) {
        int r = wid * 16 + it;
        int gr = row0 + r;
        if (gr >= M) break;
        float v0 = Cs[r * CS_LD + lane * 2];
        float v1 = Cs[r * CS_LD + lane * 2 + 1];
        float m = fmaxf(v0, v1);
        #pragma unroll
        for (int o = 16; o; o >>= 1) m = fmaxf(m, __shfl_xor_sync(0xffffffffu, m, o));
        float e0 = __expf(v0 - m);
        float e1 = __expf(v1 - m);
        float s = e0 + e1;
        #pragma unroll
        for (int o = 16; o; o >>= 1) s += __shfl_xor_sync(0xffffffffu, s, o);
        float inv = 1.0f / s;
        ((float2*)out)[(size_t)gr * 32 + lane] = make_float2(e0 * inv, e1 * inv);
    }
}

// ---------------- launch -----------------------------------------------------
extern "C" void kernel_launch(void* const* d_in, const int* in_sizes, int n_in,
                              void* d_out, int out_size) {
    const float* x      = (const float*)d_in[0];
    const int*   ei     = (const int*)d_in[1];
    const float* Wg     = (const float*)d_in[2];
    const float* bg     = (const float*)d_in[3];
    const float* ln_g   = (const float*)d_in[4];
    const float* ln_b   = (const float*)d_in[5];
    const float* mlp_W1 = (const float*)d_in[6];
    const float* mlp_b1 = (const float*)d_in[7];
    const float* mlp_W2 = (const float*)d_in[8];
    const float* mlp_b2 = (const float*)d_in[9];
    float* out = (float*)d_out;

    cudaFuncSetAttribute(k_gemm64<0>,
                         cudaFuncAttributeMaxDynamicSharedMemorySize, SMEM_TOT);
    cudaFuncSetAttribute(k_gemm64<1>,
                         cudaFuncAttributeMaxDynamicSharedMemorySize, SMEM_TOT);
    cudaFuncSetAttribute(k_gemm_w2s,
                         cudaFuncAttributeMaxDynamicSharedMemorySize, SMEM_TOT);

    const int TB = 256;
    int gE   = (EE + TB - 1) / TB;
    int gN32 = (NN * 32 + TB - 1) / TB;

    // zero hist via capturable memset, then fused init (hist count included)
    void* hist_ptr = nullptr;
    cudaGetSymbolAddress(&hist_ptr, g_hist);
    cudaMemsetAsync(hist_ptr, 0, NN * sizeof(int));

    k_initcopy<<<gN32, TB>>>(x, ei, Wg, mlp_W1, mlp_W2);
    k_scan<<<1, 1024>>>();
    k_fill<<<gE, TB>>>(ei);

    int gM = (NN + 127) / 128;   // 391
    dim3 g2(2, gM);              // N-tile fastest: pairs co-scheduled, A dedup in L2

    for (int i = 0; i < LLAYERS; i++) {
        // u = dinv * (h @ Wg[i]) -> g_hW
        k_gemm64<0><<<g2, TB, SMEM_TOT>>>(
            i * HH, XCW, WG_OFF(i), HH, nullptr, NN, 4);
        // fused gather + LN + ReLU -> xc hi/lo
        k_gather_ln<<<gN32, TB>>>(bg, ln_g, ln_b, i);
    }

    // z = relu(xc @ W1 + b1)
    k_gemm64<1><<<g2, TB, SMEM_TOT>>>(
        0, XCW, W1_OFF, HH, mlp_b1, NN, 16);

    // out = softmax(z @ W2 + b2)  (fused)
    k_gemm_w2s<<<gM, TB, SMEM_TOT>>>(mlp_b2, out, NN);
}

// round 14
// speedup vs baseline: 1.0558x; 1.0558x over previous
#include <cuda_runtime.h>
#include <cuda_bf16.h>
#include <cuda_fp16.h>
#include <cstdint>

// Problem constants
#define NN 50000
#define EE 600000
#define DD 128
#define HH 128
#define CC 64
#define LLAYERS 3
#define XCW (DD + LLAYERS * HH)   // 512

// weight split buffer offsets (elements)
#define WG_OFF(i) ((i) * 16384)
#define W1_OFF    49152
#define W2_OFF    114688
#define WB_TOT    122880

// ---------------- scratch (device globals; no runtime allocation) ----------
__device__ int   g_hist[NN];
__device__ int   g_rowptr[NN + 1];
__device__ int   g_cursor[NN];
__device__ int   g_csr_src[EE];
__device__ float g_dinv[NN];
__device__ __half g_u16[(size_t)NN * HH];   // u = dinv * (h @ W), fp16 (gather input)
__device__ __nv_bfloat16 g_xc_hi[(size_t)NN * XCW];
__device__ __nv_bfloat16 g_xc_lo[(size_t)NN * XCW];
__device__ __nv_bfloat16 g_z_hi[(size_t)NN * HH];
__device__ __nv_bfloat16 g_z_lo[(size_t)NN * HH];
__device__ __nv_bfloat16 g_wb_hi[WB_TOT];
__device__ __nv_bfloat16 g_wb_lo[WB_TOT];

__device__ __forceinline__ void split2(float2 v, __nv_bfloat162& h, __nv_bfloat162& l) {
    h = __float22bfloat162_rn(v);
    float2 f = __bfloat1622float2(h);
    l = __float22bfloat162_rn(make_float2(v.x - f.x, v.y - f.y));
}

// ---------------- setup kernels ---------------------------------------------
// fused: hist count (hist pre-zeroed by memset), split weights, copy/split x
__global__ void k_initcopy(const float* __restrict__ x,
                           const int* __restrict__ ei,
                           const float* __restrict__ Wg,
                           const float* __restrict__ W1,
                           const float* __restrict__ W2) {
    int idx = blockIdx.x * blockDim.x + threadIdx.x;
    if (idx < EE) atomicAdd(&g_hist[ei[EE + idx]], 1);
    if (idx < WB_TOT) {
        float v;
        if (idx < W1_OFF) v = Wg[idx];
        else if (idx < W2_OFF) v = W1[idx - W1_OFF];
        else v = W2[idx - W2_OFF];
        __nv_bfloat16 h = __float2bfloat16(v);
        g_wb_hi[idx] = h;
        g_wb_lo[idx] = __float2bfloat16(v - __bfloat162float(h));
    }
    if (idx >= NN * 32) return;
    int n = idx >> 5;
    int c4 = (idx & 31) << 2;
    float4 v = ((const float4*)x)[idx];
    __nv_bfloat162 h0, l0, h1, l1;
    split2(make_float2(v.x, v.y), h0, l0);
    split2(make_float2(v.z, v.w), h1, l1);
    size_t base = (size_t)n * XCW + c4;
    *(__nv_bfloat162*)&g_xc_hi[base]     = h0;
    *(__nv_bfloat162*)&g_xc_hi[base + 2] = h1;
    *(__nv_bfloat162*)&g_xc_lo[base]     = l0;
    *(__nv_bfloat162*)&g_xc_lo[base + 2] = l1;
}

// single-block exclusive scan over g_hist -> g_rowptr / g_cursor; also dinv
__global__ __launch_bounds__(1024) void k_scan() {
    const int CH = (NN + 1023) / 1024;   // 49
    int tid = threadIdx.x;
    int lane = tid & 31;
    int wid = tid >> 5;
    int beg = tid * CH;
    int end = min(beg + CH, NN);

    int s = 0;
    for (int i = beg; i < end; i++) s += g_hist[i];

    int v = s;
    #pragma unroll
    for (int o = 1; o < 32; o <<= 1) {
        int t = __shfl_up_sync(0xffffffffu, v, o);
        if (lane >= o) v += t;
    }
    __shared__ int ws[32];
    if (lane == 31) ws[wid] = v;
    __syncthreads();
    if (wid == 0) {
        int w = ws[lane];
        #pragma unroll
        for (int o = 1; o < 32; o <<= 1) {
            int t = __shfl_up_sync(0xffffffffu, w, o);
            if (lane >= o) w += t;
        }
        ws[lane] = w;
    }
    __syncthreads();
    int base = (wid ? ws[wid - 1] : 0) + v - s;   // exclusive offset
    for (int i = beg; i < end; i++) {
        g_rowptr[i] = base;
        g_cursor[i] = base;
        base += g_hist[i];
        g_dinv[i] = rsqrtf((float)(g_hist[i] + 1));
    }
    if (tid == 1023) g_rowptr[NN] = EE;
}

__global__ void k_fill(const int* __restrict__ ei) {
    int e = blockIdx.x * blockDim.x + threadIdx.x;
    if (e >= EE) return;
    int d = ei[EE + e];
    int pos = atomicAdd(&g_cursor[d], 1);
    g_csr_src[pos] = ei[e];
}

// ---------------- fused gather + LN + ReLU -----------------------------------
// warp per node d: acc = u[d] + sum_{s in N(d)} u[s] (fp16 rows, fp32 accum);
// then dinv[d]*acc + bias, LayerNorm, ReLU -> xc hi/lo
__global__ void k_gather_ln(const float* __restrict__ bg,
                            const float* __restrict__ lng,
                            const float* __restrict__ lnb,
                            int layer) {
    int t = blockIdx.x * blockDim.x + threadIdx.x;
    int w = t >> 5;
    if (w >= NN) return;
    int lane = t & 31;

    const uint2* U = (const uint2*)g_u16;   // 4 halves per lane-slot
    float4 acc;
    {
        uint2 p = __ldg(&U[(size_t)w * 32 + lane]);   // self term u[d]
        float2 f0 = __half22float2(*(__half2*)&p.x);
        float2 f1 = __half22float2(*(__half2*)&p.y);
        acc = make_float4(f0.x, f0.y, f1.x, f1.y);
    }
    int pos = __ldg(&g_rowptr[w]);
    int end = __ldg(&g_rowptr[w + 1]);

    for (; pos + 8 <= end; pos += 8) {
        int sx[8];
        #pragma unroll
        for (int j = 0; j < 8; j++) sx[j] = __ldg(&g_csr_src[pos + j]);
        uint2 pv[8];
        #pragma unroll
        for (int j = 0; j < 8; j++) pv[j] = __ldg(&U[(size_t)sx[j] * 32 + lane]);
        #pragma unroll
        for (int j = 0; j < 8; j++) {
            float2 f0 = __half22float2(*(__half2*)&pv[j].x);
            float2 f1 = __half22float2(*(__half2*)&pv[j].y);
            acc.x += f0.x; acc.y += f0.y; acc.z += f1.x; acc.w += f1.y;
        }
    }
    if (pos + 4 <= end) {
        int sx[4];
        #pragma unroll
        for (int j = 0; j < 4; j++) sx[j] = __ldg(&g_csr_src[pos + j]);
        uint2 pv[4];
        #pragma unroll
        for (int j = 0; j < 4; j++) pv[j] = __ldg(&U[(size_t)sx[j] * 32 + lane]);
        #pragma unroll
        for (int j = 0; j < 4; j++) {
            float2 f0 = __half22float2(*(__half2*)&pv[j].x);
            float2 f1 = __half22float2(*(__half2*)&pv[j].y);
            acc.x += f0.x; acc.y += f0.y; acc.z += f1.x; acc.w += f1.y;
        }
        pos += 4;
    }
    for (; pos < end; pos++) {
        int s = __ldg(&g_csr_src[pos]);
        uint2 p = __ldg(&U[(size_t)s * 32 + lane]);
        float2 f0 = __half22float2(*(__half2*)&p.x);
        float2 f1 = __half22float2(*(__half2*)&p.y);
        acc.x += f0.x; acc.y += f0.y; acc.z += f1.x; acc.w += f1.y;
    }

    float dd = __ldg(&g_dinv[w]);
    float4 bb = ((const float4*)(bg + layer * HH))[lane];
    acc.x = fmaf(acc.x, dd, bb.x);
    acc.y = fmaf(acc.y, dd, bb.y);
    acc.z = fmaf(acc.z, dd, bb.z);
    acc.w = fmaf(acc.w, dd, bb.w);

    float s = acc.x + acc.y + acc.z + acc.w;
    #pragma unroll
    for (int o = 16; o; o >>= 1) s += __shfl_xor_sync(0xffffffffu, s, o);
    float mu = s * (1.0f / HH);

    float dx = acc.x - mu, dy = acc.y - mu, dz = acc.z - mu, dw = acc.w - mu;
    float q = dx * dx + dy * dy + dz * dz + dw * dw;
    #pragma unroll
    for (int o = 16; o; o >>= 1) q += __shfl_xor_sync(0xffffffffu, q, o);
    float inv = rsqrtf(q * (1.0f / HH) + 1e-5f);

    float4 g4 = ((const float4*)(lng + layer * HH))[lane];
    float4 b4 = ((const float4*)(lnb + layer * HH))[lane];
    float4 o4;
    o4.x = fmaxf(fmaf(g4.x * dx, inv, b4.x), 0.0f);
    o4.y = fmaxf(fmaf(g4.y * dy, inv, b4.y), 0.0f);
    o4.z = fmaxf(fmaf(g4.z * dz, inv, b4.z), 0.0f);
    o4.w = fmaxf(fmaf(g4.w * dw, inv, b4.w), 0.0f);

    __nv_bfloat162 h0, l0, h1, l1;
    split2(make_float2(o4.x, o4.y), h0, l0);
    split2(make_float2(o4.z, o4.w), h1, l1);
    size_t base = (size_t)w * XCW + (1 + layer) * HH + lane * 4;
    *(__nv_bfloat162*)&g_xc_hi[base]     = h0;
    *(__nv_bfloat162*)&g_xc_hi[base + 2] = h1;
    *(__nv_bfloat162*)&g_xc_lo[base]     = l0;
    *(__nv_bfloat162*)&g_xc_lo[base + 2] = l1;
}

// ==================== cp.async bf16-split GEMM (128x64 tile, 2-stage) =======
__device__ __forceinline__ uint32_t smem_u32(const void* p) {
    uint32_t a;
    asm("{ .reg .u64 t; cvta.to.shared.u64 t, %1; cvt.u32.u64 %0, t; }"
        : "=r"(a) : "l"(p));
    return a;
}

__device__ __forceinline__ void ldm_x4(uint32_t* r, uint32_t addr) {
    asm volatile("ldmatrix.sync.aligned.m8n8.x4.shared.b16 {%0,%1,%2,%3}, [%4];"
                 : "=r"(r[0]), "=r"(r[1]), "=r"(r[2]), "=r"(r[3]) : "r"(addr));
}

__device__ __forceinline__ void ldm_x4_t(uint32_t* r, uint32_t addr) {
    asm volatile("ldmatrix.sync.aligned.m8n8.x4.trans.shared.b16 {%0,%1,%2,%3}, [%4];"
                 : "=r"(r[0]), "=r"(r[1]), "=r"(r[2]), "=r"(r[3]) : "r"(addr));
}

__device__ __forceinline__ void mma_bf16(float* d, const uint32_t* a, const uint32_t* b) {
    asm volatile("mma.sync.aligned.m16n8k16.row.col.f32.bf16.bf16.f32 "
                 "{%0,%1,%2,%3}, {%4,%5,%6,%7}, {%8,%9}, {%0,%1,%2,%3};"
                 : "+f"(d[0]), "+f"(d[1]), "+f"(d[2]), "+f"(d[3])
                 : "r"(a[0]), "r"(a[1]), "r"(a[2]), "r"(a[3]),
                   "r"(b[0]), "r"(b[1]));
}

__device__ __forceinline__ void cp16(uint32_t dst, const void* src, int sz) {
    asm volatile("cp.async.cg.shared.global [%0], [%1], 16, %2;"
                 :: "r"(dst), "l"(src), "r"(sz) : "memory");
}
#define CP_COMMIT() asm volatile("cp.async.commit_group;" ::: "memory")
#define CP_WAIT1()  asm volatile("cp.async.wait_group 1;" ::: "memory")

// smem layout (per stage): A hi rows 0..127 (80B stride), A lo at +10240;
// B hi 32x128B swizzled, B lo at +4096.
#define AST  20480
#define BOFF 40960
#define BST  8192
#define SMEM_TOT (BOFF + 2 * BST)   // 57344

__device__ __forceinline__ void issue_chunk(
    const __nv_bfloat16* __restrict__ A_hi, const __nv_bfloat16* __restrict__ A_lo,
    int lda,
    const __nv_bfloat16* __restrict__ B_hi, const __nv_bfloat16* __restrict__ B_lo,
    int ldb, int bcol, int M, int row0, int k0,
    uint32_t as, uint32_t bs, int tid) {
    #pragma unroll
    for (int j = 0; j < 2; j++) {
        int v = tid + j * 256;
        int r = v >> 2, seg = v & 3;
        int gr = row0 + r;
        int sz = (gr < M) ? 16 : 0;
        if (gr >= M) gr = 0;
        size_t so = (size_t)gr * lda + k0 + seg * 8;
        uint32_t dd = as + (uint32_t)(r * 80 + seg * 16);
        cp16(dd, A_hi + so, sz);
        cp16(dd + 10240, A_lo + so, sz);
    }
    {
        int k = tid >> 3, seg = tid & 7;
        int sw = seg ^ (k & 7);
        size_t so = (size_t)(k0 + k) * ldb + bcol + seg * 8;
        uint32_t dd = bs + (uint32_t)(k * 128 + sw * 16);
        cp16(dd, B_hi + so, 16);
        cp16(dd + 4096, B_lo + so, 16);
    }
}

// 2-stage cp.async mainloop: C-tile 128x64, BK=32, 8 warps (4x2).
__device__ __forceinline__ void gemm64_loop(
    const __nv_bfloat16* __restrict__ A_hi, const __nv_bfloat16* __restrict__ A_lo,
    int lda,
    const __nv_bfloat16* __restrict__ B_hi, const __nv_bfloat16* __restrict__ B_lo,
    int ldb, int bcol, int M, int nk, int row0, uint32_t smb,
    int tid, int warp_m, int warp_n, int lane,
    float (&d)[2][4][4]) {

    issue_chunk(A_hi, A_lo, lda, B_hi, B_lo, ldb, bcol, M, row0, 0,
                smb, smb + BOFF, tid);
    CP_COMMIT();
    if (nk > 1)
        issue_chunk(A_hi, A_lo, lda, B_hi, B_lo, ldb, bcol, M, row0, 32,
                    smb + AST, smb + BOFF + BST, tid);
    CP_COMMIT();

    for (int ck = 0; ck < nk; ck++) {
        CP_WAIT1();
        __syncthreads();

        uint32_t ab = smb + (uint32_t)((ck & 1) * AST);
        uint32_t bb = smb + (uint32_t)(BOFF + (ck & 1) * BST);
        #pragma unroll
        for (int ks = 0; ks < 2; ks++) {
            int kb = ks * 16;
            uint32_t afr[2][2][4];
            #pragma unroll
            for (int h = 0; h < 2; h++)
                #pragma unroll
                for (int mf = 0; mf < 2; mf++) {
                    int rr = warp_m * 32 + mf * 16 + (lane & 7) + ((lane >> 3) & 1) * 8;
                    int cc = kb + (lane >> 4) * 8;
                    ldm_x4(afr[h][mf], ab + (uint32_t)((h * 128 + rr) * 80 + cc * 2));
                }
            uint32_t bfr[2][4][2];
            #pragma unroll
            for (int h = 0; h < 2; h++)
                #pragma unroll
                for (int nn = 0; nn < 2; nn++) {
                    int kr = kb + ((lane >> 3) & 1) * 8 + (lane & 7);
                    int nc = warp_n * 32 + nn * 16 + (lane >> 4) * 8;
                    int chv = (nc >> 3) ^ (kr & 7);
                    uint32_t r4[4];
                    ldm_x4_t(r4, bb + (uint32_t)(h * 4096 + kr * 128 + (chv << 4)));
                    bfr[h][nn * 2][0] = r4[0]; bfr[h][nn * 2][1] = r4[1];
                    bfr[h][nn * 2 + 1][0] = r4[2]; bfr[h][nn * 2 + 1][1] = r4[3];
                }
            #pragma unroll
            for (int mf = 0; mf < 2; mf++)
                #pragma unroll
                for (int nf = 0; nf < 4; nf++) {
                    mma_bf16(d[mf][nf], afr[0][mf], bfr[0][nf]);
                    mma_bf16(d[mf][nf], afr[0][mf], bfr[1][nf]);
                    mma_bf16(d[mf][nf], afr[1][mf], bfr[0][nf]);
                }
        }
        __syncthreads();

        if (ck + 2 < nk)
            issue_chunk(A_hi, A_lo, lda, B_hi, B_lo, ldb, bcol, M, row0,
                        (ck + 2) * 32,
                        smb + (uint32_t)((ck & 1) * AST),
                        smb + (uint32_t)(BOFF + (ck & 1) * BST), tid);
        CP_COMMIT();
    }
}

// CM=0: layer GEMM (scale by dinv, store u -> g_u16 fp16); A = xc + a_off
// CM=1: W1 GEMM (bias+relu, store z hi/lo)
template <int CM>
__global__ __launch_bounds__(256, 3) void k_gemm64(
    int a_off, int lda, int wb_off, int ldb,
    const float* __restrict__ bias, int M, int nk) {

    extern __shared__ __align__(16) char sm[];

    const __nv_bfloat16* A_hi = g_xc_hi + a_off;    // resolved in device code
    const __nv_bfloat16* A_lo = g_xc_lo + a_off;

    int tid = threadIdx.x;
    int wid = tid >> 5;
    int lane = tid & 31;
    int warp_m = wid >> 1;     // 0..3
    int warp_n = wid & 1;      // 0..1
    int row0 = blockIdx.y * 128;
    int bcol = blockIdx.x * 64;
    uint32_t smb = smem_u32(sm);

    float d[2][4][4];
    #pragma unroll
    for (int mf = 0; mf < 2; mf++)
        #pragma unroll
        for (int nf = 0; nf < 4; nf++)
            #pragma unroll
            for (int j = 0; j < 4; j++) d[mf][nf][j] = 0.0f;

    gemm64_loop(A_hi, A_lo, lda, g_wb_hi + wb_off, g_wb_lo + wb_off, ldb, bcol,
                M, nk, row0, smb, tid, warp_m, warp_n, lane, d);

    #pragma unroll
    for (int mf = 0; mf < 2; mf++) {
        int rbase = row0 + warp_m * 32 + mf * 16 + (lane >> 2);
        #pragma unroll
        for (int half = 0; half < 2; half++) {
            int gr = rbase + half * 8;
            if (gr < M) {
                float sc = (CM == 0) ? __ldg(&g_dinv[gr]) : 1.0f;
                #pragma unroll
                for (int nf = 0; nf < 4; nf++) {
                    int gc = bcol + warp_n * 32 + nf * 8 + (lane & 3) * 2;
                    float2 v = make_float2(d[mf][nf][half * 2], d[mf][nf][half * 2 + 1]);
                    if (CM == 0) {
                        v.x *= sc; v.y *= sc;
                        __half2 hv = __float22half2_rn(v);
                        *(__half2*)&g_u16[(size_t)gr * HH + gc] = hv;
                    } else {
                        v.x = fmaxf(v.x + bias[gc], 0.f);
                        v.y = fmaxf(v.y + bias[gc + 1], 0.f);
                        __nv_bfloat162 h, l;
                        split2(v, h, l);
                        *(__nv_bfloat162*)&g_z_hi[(size_t)gr * HH + gc] = h;
                        *(__nv_bfloat162*)&g_z_lo[(size_t)gr * HH + gc] = l;
                    }
                }
            }
        }
    }
}

// ===== W2 GEMM (128x64) with fused bias + softmax epilogue -> out ===========
__global__ __launch_bounds__(256, 3) void k_gemm_w2s(
    const float* __restrict__ bias, float* __restrict__ out, int M) {

    extern __shared__ __align__(16) char sm[];
    constexpr int CS_LD = 66;
    float* Cs = (float*)sm;          // 128*66*4 = 33792 <= SMEM_TOT

    int tid = threadIdx.x;
    int wid = tid >> 5;
    int lane = tid & 31;
    int warp_m = wid >> 1;
    int warp_n = wid & 1;
    int row0 = blockIdx.x * 128;
    uint32_t smb = smem_u32(sm);

    float d[2][4][4];
    #pragma unroll
    for (int mf = 0; mf < 2; mf++)
        #pragma unroll
        for (int nf = 0; nf < 4; nf++)
            #pragma unroll
            for (int j = 0; j < 4; j++) d[mf][nf][j] = 0.0f;

    gemm64_loop(g_z_hi, g_z_lo, HH, g_wb_hi + W2_OFF, g_wb_lo + W2_OFF, CC, 0,
                M, 4, row0, smb, tid, warp_m, warp_n, lane, d);
    // loop ends with a __syncthreads after final compute: smem reusable

    #pragma unroll
    for (int mf = 0; mf < 2; mf++) {
        int rl = warp_m * 32 + mf * 16 + (lane >> 2);
        #pragma unroll
        for (int half = 0; half < 2; half++) {
            int r = rl + half * 8;
            #pragma unroll
            for (int nf = 0; nf < 4; nf++) {
                int c = warp_n * 32 + nf * 8 + (lane & 3) * 2;
                Cs[r * CS_LD + c]     = d[mf][nf][half * 2]     + bias[c];
                Cs[r * CS_LD + c + 1] = d[mf][nf][half * 2 + 1] + bias[c + 1];
            }
        }
    }
    __syncthreads();

    for (int it = 0; it < 16; it++) {
        int r = wid * 16 + it;
        int gr = row0 + r;
        if (gr >= M) break;
        float v0 = Cs[r * CS_LD + lane * 2];
        float v1 = Cs[r * CS_LD + lane * 2 + 1];
        float m = fmaxf(v0, v1);
        #pragma unroll
        for (int o = 16; o; o >>= 1) m = fmaxf(m, __shfl_xor_sync(0xffffffffu, m, o));
        float e0 = __expf(v0 - m);
        float e1 = __expf(v1 - m);
        float s = e0 + e1;
        #pragma unroll
        for (int o = 16; o; o >>= 1) s += __shfl_xor_sync(0xffffffffu, s, o);
        float inv = 1.0f / s;
        ((float2*)out)[(size_t)gr * 32 + lane] = make_float2(e0 * inv, e1 * inv);
    }
}

// ---------------- launch -----------------------------------------------------
extern "C" void kernel_launch(void* const* d_in, const int* in_sizes, int n_in,
                              void* d_out, int out_size) {
    const float* x      = (const float*)d_in[0];
    const int*   ei     = (const int*)d_in[1];
    const float* Wg     = (const float*)d_in[2];
    const float* bg     = (const float*)d_in[3];
    const float* ln_g   = (const float*)d_in[4];
    const float* ln_b   = (const float*)d_in[5];
    const float* mlp_W1 = (const float*)d_in[6];
    const float* mlp_b1 = (const float*)d_in[7];
    const float* mlp_W2 = (const float*)d_in[8];
    const float* mlp_b2 = (const float*)d_in[9];
    float* out = (float*)d_out;

    cudaFuncSetAttribute(k_gemm64<0>,
                         cudaFuncAttributeMaxDynamicSharedMemorySize, SMEM_TOT);
    cudaFuncSetAttribute(k_gemm64<1>,
                         cudaFuncAttributeMaxDynamicSharedMemorySize, SMEM_TOT);
    cudaFuncSetAttribute(k_gemm_w2s,
                         cudaFuncAttributeMaxDynamicSharedMemorySize, SMEM_TOT);

    const int TB = 256;
    int gE   = (EE + TB - 1) / TB;
    int gN32 = (NN * 32 + TB - 1) / TB;

    // zero hist via capturable memset, then fused init (hist count included)
    void* hist_ptr = nullptr;
    cudaGetSymbolAddress(&hist_ptr, g_hist);
    cudaMemsetAsync(hist_ptr, 0, NN * sizeof(int));

    k_initcopy<<<gN32, TB>>>(x, ei, Wg, mlp_W1, mlp_W2);
    k_scan<<<1, 1024>>>();
    k_fill<<<gE, TB>>>(ei);

    int gM = (NN + 127) / 128;   // 391
    dim3 g2(2, gM);              // N-tile fastest: pairs co-scheduled, A dedup in L2

    for (int i = 0; i < LLAYERS; i++) {
        // u = dinv * (h @ Wg[i]) -> g_u16 (fp16)
        k_gemm64<0><<<g2, TB, SMEM_TOT>>>(
            i * HH, XCW, WG_OFF(i), HH, nullptr, NN, 4);
        // fused gather + LN + ReLU -> xc hi/lo
        k_gather_ln<<<gN32, TB>>>(bg, ln_g, ln_b, i);
    }

    // z = relu(xc @ W1 + b1)
    k_gemm64<1><<<g2, TB, SMEM_TOT>>>(
        0, XCW, W1_OFF, HH, mlp_b1, NN, 16);

    // out = softmax(z @ W2 + b2)  (fused)
    k_gemm_w2s<<<gM, TB, SMEM_TOT>>>(mlp_b2, out, NN);
}